// round 2
// baseline (speedup 1.0000x reference)
#include <cuda_runtime.h>
#include <math.h>
#include <stdint.h>

#define DD 512
#define PP 36
#define NT 512
#define EPSN 1e-12f
#define SCALE_CLS 7.0f

#define TILE_F (PP*DD)            // 18432 floats, tile stored [P][D]
// SMEM float offsets
#define MEANO 18432               // own mean (512)
#define MEANP (MEANO+512)         // peer mean (512)
#define VBUF  (MEANP+512)         // peer fused vector (512)
#define SCOFF (VBUF+512)          // selection scores (36)
#define NOFF  (SCOFF+36)          // per-position norms (36)
#define WOFF  (NOFF+36)           // fuse weights (36)
#define REDOFF (WOFF+36)          // 48-float reduction scratch
#define UUOFF (REDOFF+48)         // own uu total
#define VVOFF (UUOFF+1)           // peer vv total
#define SMEMF (VVOFF+3)
#define SMEMB (SMEMF*4)           // ~80.5 KB -> 2 CTAs/SM

__device__ __forceinline__ float warp_sum(float v) {
#pragma unroll
    for (int o = 16; o > 0; o >>= 1) v += __shfl_down_sync(0xffffffffu, v, o);
    return v;
}

__device__ __forceinline__ float dot4(float4 a, float4 b) {
    return a.x*b.x + a.y*b.y + a.z*b.z + a.w*b.w;
}

__device__ __forceinline__ uint32_t smem_u32(const void* p) {
    uint32_t a;
    asm("{ .reg .u64 t; cvta.to.shared.u64 t, %1; cvt.u32.u64 %0, t; }"
        : "=r"(a) : "l"(p));
    return a;
}

// store a float into the peer CTA's SMEM at the same offset
__device__ __forceinline__ void st_cluster_f32(uint32_t laddr, uint32_t peer_rank, float v) {
    uint32_t r;
    asm volatile("mapa.shared::cluster.u32 %0, %1, %2;" : "=r"(r) : "r"(laddr), "r"(peer_rank));
    asm volatile("st.shared::cluster.f32 [%0], %1;" :: "r"(r), "f"(v) : "memory");
}

#define CLUSTER_SYNC() do { \
    asm volatile("barrier.cluster.arrive.aligned;" ::: "memory"); \
    asm volatile("barrier.cluster.wait.aligned;"   ::: "memory"); \
} while (0)

__global__ __launch_bounds__(NT, 2) __cluster_dims__(2, 1, 1)
void fused_region_score_cluster(const float* __restrict__ ftrain,
                                const float* __restrict__ ftest,
                                const int*   __restrict__ Kp,
                                float* __restrict__ out,
                                int halfOut)
{
    extern __shared__ float sm[];
    float* red = sm + REDOFF;

    const int g    = blockIdx.x >> 1;
    const int role = blockIdx.x & 1;        // 0 = test tensor, 1 = train tensor
    const int tid  = threadIdx.x;
    const int lane = tid & 31;
    const int wid  = tid >> 5;
    const uint32_t peer = (uint32_t)(role ^ 1);
    const uint32_t smbase = smem_u32(sm);
    const int K = Kp[0];

    // ---------------- load own tensor row (thread = d), transpose into SMEM,
    // ---------------- compute spatial mean in registers ---------------------
    const float* src = (role ? ftrain : ftest) + (size_t)g * TILE_F;
    const float4* s4 = (const float4*)src + tid * 9;

    float4 r0 = s4[0], r1 = s4[1], r2 = s4[2], r3 = s4[3], r4 = s4[4],
           r5 = s4[5], r6 = s4[6], r7 = s4[7], r8 = s4[8];
    float4 rr[9] = {r0,r1,r2,r3,r4,r5,r6,r7,r8};
    float sum = 0.f;
#pragma unroll
    for (int k = 0; k < 9; k++) {
        sm[(4*k+0)*DD + tid] = rr[k].x;
        sm[(4*k+1)*DD + tid] = rr[k].y;
        sm[(4*k+2)*DD + tid] = rr[k].z;
        sm[(4*k+3)*DD + tid] = rr[k].w;
        sum += rr[k].x + rr[k].y + rr[k].z + rr[k].w;
    }
    const float m = sum * (1.0f / (float)PP);
    sm[MEANO + tid] = m;
    // push own mean to peer's MEANP buffer
    st_cluster_f32(smbase + (MEANP + tid) * 4u, peer, m);

    CLUSTER_SYNC();   // tile local-visible, means exchanged

    // ---------------- role 0: global score out[g] ----------------------------
    if (role == 0) {
        float mp = sm[MEANP + tid];
        float a = warp_sum(m * mp);
        float b = warp_sum(m * m);
        float c = warp_sum(mp * mp);
        if (lane == 0) { red[wid] = a; red[16+wid] = b; red[32+wid] = c; }
        __syncthreads();
        if (wid == 0) {
            float x = (lane < 16) ? red[lane]      : 0.f;
            float y = (lane < 16) ? red[16 + lane] : 0.f;
            float z = (lane < 16) ? red[32 + lane] : 0.f;
            x = warp_sum(x); y = warp_sum(y); z = warp_sum(z);
            if (lane == 0) {
                float denom = fmaxf(sqrtf(y), EPSN) * fmaxf(sqrtf(z), EPSN);
                out[g] = SCALE_CLS * x / denom;
            }
        }
    }

    // ---------------- stage B: per-position norm + selection score ----------
    // tile is [P][D]; warp w handles p = w, w+16, (w+32 if w<4)
    {
        const float4* t4 = (const float4*)sm;          // row p = 128 float4
        const float4* m4 = (const float4*)(sm + MEANP);
        const int p0 = wid, p1 = wid + 16, p2 = wid + 32;
        float a20 = 0.f, ta0 = 0.f, a21 = 0.f, ta1 = 0.f, a22 = 0.f, ta2 = 0.f;
#pragma unroll
        for (int i = 0; i < 4; i++) {
            int idx = lane + 32 * i;
            float4 mm = m4[idx];
            float4 a = t4[p0 * 128 + idx];
            a20 += dot4(a, a);  ta0 += dot4(a, mm);
            float4 b = t4[p1 * 128 + idx];
            a21 += dot4(b, b);  ta1 += dot4(b, mm);
            if (wid < 4) {
                float4 c = t4[p2 * 128 + idx];
                a22 += dot4(c, c);  ta2 += dot4(c, mm);
            }
        }
        a20 = warp_sum(a20); ta0 = warp_sum(ta0);
        a21 = warp_sum(a21); ta1 = warp_sum(ta1);
        if (lane == 0) {
            float n0 = fmaxf(sqrtf(a20), EPSN);
            float n1 = fmaxf(sqrtf(a21), EPSN);
            sm[NOFF + p0]  = n0;  sm[SCOFF + p0] = ta0 / n0;
            sm[NOFF + p1]  = n1;  sm[SCOFF + p1] = ta1 / n1;
        }
        if (wid < 4) {
            a22 = warp_sum(a22); ta2 = warp_sum(ta2);
            if (lane == 0) {
                float n2 = fmaxf(sqrtf(a22), EPSN);
                sm[NOFF + p2] = n2;  sm[SCOFF + p2] = ta2 / n2;
            }
        }
    }
    __syncthreads();

    // ---------------- stage C: top-K via rank counting ----------------------
    if (tid < PP) {
        const float sv = sm[SCOFF + tid];
        int rank = 0;
#pragma unroll
        for (int q = 0; q < PP; q++) {
            float o = sm[SCOFF + q];
            rank += (o > sv) || (o == sv && q < tid);  // lower index wins ties
        }
        sm[WOFF + tid] = (rank < K) ? (1.0f / sm[NOFF + tid]) : 0.0f;
    }
    __syncthreads();

    // ---------------- stage D: fused vector + norms + exchange --------------
    float u = 0.f;
#pragma unroll
    for (int p = 0; p < PP; p++)
        u += sm[p * DD + tid] * sm[WOFF + p];

    if (role == 1)   // push fused vector to role-0's VBUF
        st_cluster_f32(smbase + (VBUF + tid) * 4u, 0u, u);

    float uu = warp_sum(u * u);
    if (lane == 0) red[wid] = uu;
    __syncthreads();
    if (wid == 0) {
        float x = (lane < 16) ? red[lane] : 0.f;
        x = warp_sum(x);
        if (lane == 0) {
            sm[UUOFF] = x;
            if (role == 1)
                st_cluster_f32(smbase + VVOFF * 4u, 0u, x);  // peer's VVOFF
        }
    }

    CLUSTER_SYNC();   // v vector + vv delivered to role 0

    // ---------------- role 0: final score ------------------------------------
    if (role == 0) {
        float uv = warp_sum(u * sm[VBUF + tid]);
        if (lane == 0) red[wid] = uv;
        __syncthreads();
        if (wid == 0) {
            float x = (lane < 16) ? red[lane] : 0.f;
            x = warp_sum(x);
            if (lane == 0) {
                float uu_t = sm[UUOFF];
                float vv_t = sm[VVOFF];
                float denom = fmaxf(sqrtf(uu_t), EPSN) * fmaxf(sqrtf(vv_t), EPSN);
                out[halfOut + g] = SCALE_CLS * x / denom;
            }
        }
    }
}

extern "C" void kernel_launch(void* const* d_in, const int* in_sizes, int n_in,
                              void* d_out, int out_size)
{
    const float* ftrain = (const float*)d_in[0];
    const float* ftest  = (const float*)d_in[1];
    const int*   Kp     = (const int*)d_in[2];
    float* out = (float*)d_out;

    const int groups  = in_sizes[0] / (DD * PP);   // 1500
    const int halfOut = out_size / 2;              // 1500

    cudaFuncSetAttribute(fused_region_score_cluster,
                         cudaFuncAttributeMaxDynamicSharedMemorySize, SMEMB);
    fused_region_score_cluster<<<groups * 2, NT, SMEMB>>>(
        ftrain, ftest, Kp, out, halfOut);
}